// round 3
// baseline (speedup 1.0000x reference)
#include <cuda_runtime.h>
#include <cuda_bf16.h>

// Problem constants (fixed by the reference)
#define BB  4
#define LL  512
#define HH  768
#define SS  100
#define RR  100
#define EE  25
#define NE  10
#define NR  6
#define NEGV (-1e20f)

#define H4 (HH/4)          // 192 float4 lanes per row
#define SPAN_DIM (HH + EE)             // 793
#define REL_DIM  (3*HH + 2*EE)         // 2354

// Scratch (static device globals — no runtime allocation)
__device__ float g_ent[BB*SS*HH];   // pooled entity reprs
__device__ float g_esz[BB*SS*EE];   // entity size embeddings
__device__ float g_ctx[BB*RR*HH];   // pooled relation-context reprs

// -----------------------------------------------------------------------------
// K1: blocks [0, B*S)      -> entity pooling + size emb + entity logits
//     blocks [B*S, B*S+B*R)-> relation-context pooling
// -----------------------------------------------------------------------------
__global__ void __launch_bounds__(256)
spert_pool_entity_kernel(const float* __restrict__ hid,
                         const int*   __restrict__ emask,
                         const int*   __restrict__ cmask,
                         const float* __restrict__ size_emb,
                         const float* __restrict__ w_span,
                         const float* __restrict__ b_span,
                         float*       __restrict__ out)
{
    __shared__ __align__(16) float repr[SPAN_DIM];
    __shared__ int s_start;
    __shared__ int s_len;

    const int bid    = blockIdx.x;
    const bool is_ent = (bid < BB*SS);
    const int idx    = is_ent ? bid : bid - BB*SS;   // b*N + n
    const int b      = idx / SS;
    const int t      = threadIdx.x;

    // ---- recover contiguous span (start, len) from the 0/1 mask row ----
    const int* mrow = (is_ent ? emask : cmask) + (size_t)idx * LL;
    if (t == 0) { s_start = LL; s_len = 0; }
    __syncthreads();
    #pragma unroll
    for (int l = t; l < LL; l += 256) {
        if (mrow[l]) { atomicAdd(&s_len, 1); atomicMin(&s_start, l); }
    }
    __syncthreads();
    const int start = s_start;
    const int len   = s_len;

    // ---- masked max pool over the span (float4 vectorized) ----
    if (t < H4) {
        float4 mx = make_float4(NEGV, NEGV, NEGV, NEGV);
        const float4* hbase = reinterpret_cast<const float4*>(hid + (size_t)b * LL * HH) + t;
        for (int l = start; l < start + len; ++l) {
            float4 v = hbase[(size_t)l * H4];
            mx.x = fmaxf(mx.x, v.x); mx.y = fmaxf(mx.y, v.y);
            mx.z = fmaxf(mx.z, v.z); mx.w = fmaxf(mx.w, v.w);
        }
        if (is_ent) {
            reinterpret_cast<float4*>(repr)[t] = mx;
            reinterpret_cast<float4*>(g_ent + (size_t)idx * HH)[t] = mx;
        } else {
            reinterpret_cast<float4*>(g_ctx + (size_t)idx * HH)[t] = mx;
        }
    }

    if (is_ent) {
        // size embedding: size_emb[len] (len < 100 by construction)
        if (t < EE) {
            float v = size_emb[len * EE + t];
            repr[HH + t] = v;
            g_esz[idx * EE + t] = v;
        }
        __syncthreads();

        // entity logits: warp-per-output-column dot over 793-dim repr
        const int warp = t >> 5, lane = t & 31;
        for (int j = warp; j < NE; j += 8) {
            float acc = 0.f;
            for (int k = lane; k < SPAN_DIM; k += 32)
                acc += repr[k] * __ldg(&w_span[k * NE + j]);
            #pragma unroll
            for (int o = 16; o; o >>= 1)
                acc += __shfl_down_sync(0xffffffffu, acc, o);
            if (lane == 0)
                out[idx * NE + j] = acc + __ldg(&b_span[j]);
        }
    }
}

// -----------------------------------------------------------------------------
// K2: one block per (b, r): gather ctx + head/tail entity + sizes, rel logits
// -----------------------------------------------------------------------------
__global__ void __launch_bounds__(256)
spert_relation_kernel(const int*   __restrict__ rel,
                      const float* __restrict__ w_rel,
                      const float* __restrict__ b_rel,
                      float*       __restrict__ out)
{
    __shared__ __align__(16) float repr[REL_DIM];   // [ctx | ent_h | ent_t | sz_h | sz_t]

    const int bid = blockIdx.x;          // = b*R + r
    const int b   = bid / RR;
    const int t   = threadIdx.x;

    const int hi = rel[bid * 2 + 0];
    const int ti = rel[bid * 2 + 1];

    const float4* ctx = reinterpret_cast<const float4*>(g_ctx + (size_t)bid * HH);
    const float4* eh  = reinterpret_cast<const float4*>(g_ent + (size_t)(b * SS + hi) * HH);
    const float4* et  = reinterpret_cast<const float4*>(g_ent + (size_t)(b * SS + ti) * HH);

    if (t < H4) {
        reinterpret_cast<float4*>(repr)[t]          = ctx[t];
        reinterpret_cast<float4*>(repr)[H4 + t]     = eh[t];
        reinterpret_cast<float4*>(repr)[2 * H4 + t] = et[t];
    }
    if (t < EE) {
        repr[3 * HH + t]      = g_esz[(b * SS + hi) * EE + t];
        repr[3 * HH + EE + t] = g_esz[(b * SS + ti) * EE + t];
    }
    __syncthreads();

    const int warp = t >> 5, lane = t & 31;
    for (int j = warp; j < NR; j += 8) {
        float acc = 0.f;
        for (int k = lane; k < REL_DIM; k += 32)
            acc += repr[k] * __ldg(&w_rel[k * NR + j]);
        #pragma unroll
        for (int o = 16; o; o >>= 1)
            acc += __shfl_down_sync(0xffffffffu, acc, o);
        if (lane == 0)
            out[BB * SS * NE + bid * NR + j] = acc + __ldg(&b_rel[j]);
    }
}

// -----------------------------------------------------------------------------
// kernel_launch: inputs per metadata order:
//   0 hidden_states (f32)  1 entity_masks (i32)  2 relations (i32)
//   3 relation_context_masks (i32)  4 size_emb (f32)
//   5 w_span (f32)  6 b_span (f32)  7 w_rel (f32)  8 b_rel (f32)
// out: 6400 f32 = entity_logits (4000) ++ relation_logits (2400)
// -----------------------------------------------------------------------------
extern "C" void kernel_launch(void* const* d_in, const int* in_sizes, int n_in,
                              void* d_out, int out_size)
{
    const float* hid      = (const float*)d_in[0];
    const int*   emask    = (const int*)  d_in[1];
    const int*   rel      = (const int*)  d_in[2];
    const int*   cmask    = (const int*)  d_in[3];
    const float* size_emb = (const float*)d_in[4];
    const float* w_span   = (const float*)d_in[5];
    const float* b_span   = (const float*)d_in[6];
    const float* w_rel    = (const float*)d_in[7];
    const float* b_rel    = (const float*)d_in[8];
    float* out = (float*)d_out;

    spert_pool_entity_kernel<<<BB*SS + BB*RR, 256>>>(hid, emask, cmask, size_emb,
                                                     w_span, b_span, out);
    spert_relation_kernel<<<BB*RR, 256>>>(rel, w_rel, b_rel, out);
}